// round 11
// baseline (speedup 1.0000x reference)
#include <cuda_runtime.h>
#include <cuda_fp16.h>
#include <math_constants.h>
#include <cstdint>

// Problem constants: B=512, D=256, C=100000, m=4, lambda=1000
#define MAX_C 100000
#define MAX_B 512
#define DD    256

__device__ __half g_wh[(size_t)MAX_C * DD];   // fp16(normalized W)
__device__ __half g_xh[(size_t)MAX_B * DD];   // fp16(normalized X)
__device__ float  g_xlen[MAX_B];

// ---------------------------------------------------------------------------
// Helpers
// ---------------------------------------------------------------------------
__device__ __forceinline__ uint32_t smem_u32(const void* p) {
    uint32_t a;
    asm("{ .reg .u64 t; cvta.to.shared.u64 t, %1; cvt.u32.u64 %0, t; }" : "=r"(a) : "l"(p));
    return a;
}
__device__ __forceinline__ void cp_async16(uint32_t dst, const void* src) {
    asm volatile("cp.async.cg.shared.global [%0], [%1], 16;" :: "r"(dst), "l"(src));
}
__device__ __forceinline__ void cp_commit() {
    asm volatile("cp.async.commit_group;" ::: "memory");
}
template <int N> __device__ __forceinline__ void cp_wait() {
    asm volatile("cp.async.wait_group %0;" :: "n"(N) : "memory");
}
__device__ __forceinline__ void ldsm_x4(uint32_t& r0, uint32_t& r1, uint32_t& r2, uint32_t& r3,
                                        uint32_t addr) {
    asm volatile("ldmatrix.sync.aligned.m8n8.x4.shared.b16 {%0,%1,%2,%3}, [%4];"
                 : "=r"(r0), "=r"(r1), "=r"(r2), "=r"(r3) : "r"(addr));
}
__device__ __forceinline__ void mma_16816(float& c0, float& c1, float& c2, float& c3,
                                          uint32_t a0, uint32_t a1, uint32_t a2, uint32_t a3,
                                          uint32_t b0, uint32_t b1) {
    asm volatile("mma.sync.aligned.m16n8k16.row.col.f32.f16.f16.f32 "
                 "{%0,%1,%2,%3}, {%4,%5,%6,%7}, {%8,%9}, {%0,%1,%2,%3};"
                 : "+f"(c0), "+f"(c1), "+f"(c2), "+f"(c3)
                 : "r"(a0), "r"(a1), "r"(a2), "r"(a3), "r"(b0), "r"(b1));
}

// ---------------------------------------------------------------------------
// Merged prep: rows [0,C) -> normalize W row; rows [C,C+B) -> normalize X row.
// ---------------------------------------------------------------------------
__global__ void prep_kernel(const float* __restrict__ W, const float* __restrict__ X,
                            int C, int B) {
    int row  = (blockIdx.x * blockDim.x + threadIdx.x) >> 5;
    int lane = threadIdx.x & 31;
    if (row >= C + B) return;
    const bool isx = row >= C;
    const int  r   = isx ? row - C : row;
    const float* src = (isx ? X : W) + (size_t)r * DD;
    __half*      dst = (isx ? g_xh : g_wh) + (size_t)r * DD;

    float4 v0 = *(const float4*)(src + lane * 4);
    float4 v1 = *(const float4*)(src + 128 + lane * 4);
    float s = v0.x*v0.x + v0.y*v0.y + v0.z*v0.z + v0.w*v0.w
            + v1.x*v1.x + v1.y*v1.y + v1.z*v1.z + v1.w*v1.w;
    #pragma unroll
    for (int o = 16; o; o >>= 1) s += __shfl_xor_sync(0xffffffffu, s, o);
    float inv = rsqrtf(s);
    if (isx && lane == 0) g_xlen[r] = s * inv;   // len
    __half2 h0 = __floats2half2_rn(v0.x * inv, v0.y * inv);
    __half2 h1 = __floats2half2_rn(v0.z * inv, v0.w * inv);
    __half2 h2 = __floats2half2_rn(v1.x * inv, v1.y * inv);
    __half2 h3 = __floats2half2_rn(v1.z * inv, v1.w * inv);
    *(__half2*)(dst + lane * 4)           = h0;
    *(__half2*)(dst + lane * 4 + 2)       = h1;
    *(__half2*)(dst + 128 + lane * 4)     = h2;
    *(__half2*)(dst + 128 + lane * 4 + 2) = h3;
}

// ---------------------------------------------------------------------------
// GEMM: CTA 64x128, 256 threads, 8 warps (2m x 4n), warp tile 32x32.
// A+B staged together in a ring of 3 (24 KB/stage); 72 KB/CTA -> 3 CTAs/SM
// = 24 warps/SM. ks fragment double-buffering.
// ---------------------------------------------------------------------------
#define BM 64
#define BN 128
#define BK 64
#define NCHUNK (DD / BK)                 // 4

#define STAGE_BYTES 24576                // A 8 KB + B 16 KB
#define A_IN_STAGE  0
#define B_IN_STAGE  8192
#define SMEM_TOTAL  (3 * STAGE_BYTES)    // 73728 -> 3 CTAs/SM

__global__ __launch_bounds__(256, 3)
void angle_mma_kernel(const int* __restrict__ Y, float* __restrict__ out, int C)
{
    extern __shared__ char smem[];
    const uint32_t sbase = smem_u32(smem);
    const int tid  = threadIdx.x;
    const int wid  = tid >> 5;
    const int lane = tid & 31;
    const int wm   = wid >> 2;     // 0..1 : warp m (32 rows)
    const int wn   = wid & 3;      // 0..3 : warp n (32 cols)

    const int bm = blockIdx.x * BM;
    const int bn = blockIdx.y * BN;

    // ---- chunk loader: A (64x64k, 8 KB) + B (128x64k, 16 KB) into stage ----
    auto load_chunk = [&](int stage, int kc) {
        const uint32_t sb = sbase + (uint32_t)stage * STAGE_BYTES;
        // A: 512 x 16B
        #pragma unroll
        for (int i = 0; i < 2; i++) {
            int g = tid + i * 256;               // 0..511
            int row = g >> 3, blk = g & 7;
            uint32_t off = (uint32_t)(row * 128) + (uint32_t)((blk ^ (row & 7)) << 4);
            cp_async16(sb + A_IN_STAGE + off,
                       g_xh + (size_t)(bm + row) * DD + kc + blk * 8);
        }
        // B: 1024 x 16B
        #pragma unroll
        for (int i = 0; i < 4; i++) {
            int g = tid + i * 256;               // 0..1023
            int row = g >> 3, blk = g & 7;
            int rg = bn + row; if (rg >= C) rg = C - 1;
            uint32_t off = (uint32_t)(row * 128) + (uint32_t)((blk ^ (row & 7)) << 4);
            cp_async16(sb + B_IN_STAGE + off,
                       g_wh + (size_t)rg * DD + kc + blk * 8);
        }
        cp_commit();
    };

    // ---- prologue: chunks 0, 1 ----
    load_chunk(0, 0);
    load_chunk(1, BK);

    float c[2][4][4];
    #pragma unroll
    for (int mt = 0; mt < 2; mt++)
        #pragma unroll
        for (int nt = 0; nt < 4; nt++)
            #pragma unroll
            for (int q = 0; q < 4; q++) c[mt][nt][q] = 0.f;

    // XOR-composable fragment row bases: rel = row*128 + ((row&7)<<4)
    const int a_hi = lane >> 4;
    uint32_t a_rel[2], b_rel[2];
    #pragma unroll
    for (int mt = 0; mt < 2; mt++) {
        int r = wm * 32 + mt * 16 + (lane & 15);
        a_rel[mt] = (uint32_t)(r * 128) + (uint32_t)((r & 7) << 4);
    }
    #pragma unroll
    for (int bt = 0; bt < 2; bt++) {
        int r = wn * 32 + bt * 16 + ((lane >> 3) & 1) * 8 + (lane & 7);
        b_rel[bt] = (uint32_t)(r * 128) + (uint32_t)((r & 7) << 4);
    }

    // ---- main loop: one barrier per chunk; ks-pipelined fragments ----
    #pragma unroll
    for (int ck = 0; ck < NCHUNK; ck++) {
        if (ck == NCHUNK - 1) cp_wait<0>(); else cp_wait<1>();
        __syncthreads();                          // stage[ck%3] visible

        if (ck + 2 < NCHUNK) load_chunk((ck + 2) % 3, (ck + 2) * BK);

        const uint32_t sb = sbase + (uint32_t)(ck % 3) * STAGE_BYTES;
        const uint32_t ab = sb + A_IN_STAGE;
        const uint32_t bb = sb + B_IN_STAGE;

        uint32_t a[2][2][4], b[2][2][4];
        const uint32_t k0 = (uint32_t)(a_hi << 4);
        #pragma unroll
        for (int mt = 0; mt < 2; mt++)
            ldsm_x4(a[0][mt][0], a[0][mt][1], a[0][mt][2], a[0][mt][3],
                    ab + (a_rel[mt] ^ k0));
        #pragma unroll
        for (int bt = 0; bt < 2; bt++)
            ldsm_x4(b[0][bt][0], b[0][bt][1], b[0][bt][2], b[0][bt][3],
                    bb + (b_rel[bt] ^ k0));

        #pragma unroll
        for (int ks = 0; ks < 4; ks++) {
            const int cur = ks & 1, nxt = cur ^ 1;
            if (ks < 3) {
                const uint32_t kc = (uint32_t)(((ks + 1) * 2 + a_hi) << 4);
                #pragma unroll
                for (int mt = 0; mt < 2; mt++)
                    ldsm_x4(a[nxt][mt][0], a[nxt][mt][1], a[nxt][mt][2], a[nxt][mt][3],
                            ab + (a_rel[mt] ^ kc));
                #pragma unroll
                for (int bt = 0; bt < 2; bt++)
                    ldsm_x4(b[nxt][bt][0], b[nxt][bt][1], b[nxt][bt][2], b[nxt][bt][3],
                            bb + (b_rel[bt] ^ kc));
            }
            #pragma unroll
            for (int mt = 0; mt < 2; mt++) {
                #pragma unroll
                for (int nt = 0; nt < 4; nt++) {
                    const int bt = nt >> 1, sub = nt & 1;
                    mma_16816(c[mt][nt][0], c[mt][nt][1], c[mt][nt][2], c[mt][nt][3],
                              a[cur][mt][0], a[cur][mt][1], a[cur][mt][2], a[cur][mt][3],
                              b[cur][bt][sub], b[cur][bt][2 + sub]);
                }
            }
        }
    }

    // ---- epilogue: cos -> feat (+ margin at label) ----
    const float inv_pi     = 1.0f / CUDART_PI_F;
    const float inv_1plamb = 1.0f / 1001.0f;

    #pragma unroll
    for (int mt = 0; mt < 2; mt++) {
        const int r0 = bm + wm * 32 + mt * 16 + (lane >> 2);
        const int r1 = r0 + 8;
        const float xl0 = g_xlen[r0], xl1 = g_xlen[r1];
        const int  lab0 = Y[r0],      lab1 = Y[r1];
        #pragma unroll
        for (int nt = 0; nt < 4; nt++) {
            const int col = bn + wn * 32 + nt * 8 + (lane & 3) * 2;
            if (col >= C) continue;          // col even, C even -> col+1 valid
            #pragma unroll
            for (int half = 0; half < 2; half++) {
                const int   rr  = half ? r1 : r0;
                const float xl  = half ? xl1 : xl0;
                const int   lab = half ? lab1 : lab0;
                float v0 = c[mt][nt][half * 2 + 0];
                float v1 = c[mt][nt][half * 2 + 1];
                v0 = fminf(fmaxf(v0, -1.0f), 1.0f);
                v1 = fminf(fmaxf(v1, -1.0f), 1.0f);
                float f0 = v0 * xl, f1 = v1 * xl;
                if (col == lab || col + 1 == lab) {
                    const bool second = (col + 1 == lab);
                    float cv = second ? v1 : v0;
                    float c2   = cv * cv;
                    float cosm = 8.0f * c2 * c2 - 8.0f * c2 + 1.0f;
                    float kf   = floorf(4.0f * acosf(cv) * inv_pi);
                    float sign = 1.0f - 2.0f * fmodf(kf, 2.0f);
                    float phi  = sign * cosm - 2.0f * kf;
                    float fm   = second ? f1 : f0;
                    fm += (phi * xl - fm) * inv_1plamb;
                    if (second) f1 = fm; else f0 = fm;
                }
                *(float2*)(out + (size_t)rr * C + col) = make_float2(f0, f1);
            }
        }
    }
}

// ---------------------------------------------------------------------------
// Launch
// ---------------------------------------------------------------------------
extern "C" void kernel_launch(void* const* d_in, const int* in_sizes, int n_in,
                              void* d_out, int out_size)
{
    const float* x = (const float*)d_in[0];
    const float* w = (const float*)d_in[1];
    const int*   y = (const int*)d_in[2];
    float* out     = (float*)d_out;

    const int B = in_sizes[2];            // 512
    const int D = in_sizes[0] / B;        // 256
    const int C = in_sizes[1] / D;        // 100000
    (void)D;

    static bool attr_set = false;
    if (!attr_set) {
        cudaFuncSetAttribute(angle_mma_kernel,
                             cudaFuncAttributeMaxDynamicSharedMemorySize, SMEM_TOTAL);
        attr_set = true;
    }

    {
        int wpb = 8;
        int rows = C + B;
        prep_kernel<<<(rows + wpb - 1) / wpb, wpb * 32>>>(w, x, C, B);
    }

    // grid.x = m tiles (fastest -> 8 CTAs share each W n-stripe in L2)
    dim3 grid(B / BM, (C + BN - 1) / BN);
    angle_mma_kernel<<<grid, 256, SMEM_TOTAL>>>(y, out, C);
}

// round 12
// speedup vs baseline: 1.0423x; 1.0423x over previous
#include <cuda_runtime.h>
#include <cuda_fp16.h>
#include <math_constants.h>
#include <cstdint>

// Problem constants: B=512, D=256, C=100000, m=4, lambda=1000
#define MAX_C 100000
#define MAX_B 512
#define DD    256

__device__ __half g_wh[(size_t)MAX_C * DD];   // fp16(normalized W)
__device__ __half g_xh[(size_t)MAX_B * DD];   // fp16(normalized X)
__device__ float  g_xlen[MAX_B];

// ---------------------------------------------------------------------------
// Helpers
// ---------------------------------------------------------------------------
__device__ __forceinline__ uint32_t smem_u32(const void* p) {
    uint32_t a;
    asm("{ .reg .u64 t; cvta.to.shared.u64 t, %1; cvt.u32.u64 %0, t; }" : "=r"(a) : "l"(p));
    return a;
}
__device__ __forceinline__ void cp_async16(uint32_t dst, const void* src) {
    asm volatile("cp.async.cg.shared.global [%0], [%1], 16;" :: "r"(dst), "l"(src));
}
__device__ __forceinline__ void cp_async_mbar_arrive(uint32_t mbar) {
    asm volatile("cp.async.mbarrier.arrive.noinc.shared.b64 [%0];" :: "r"(mbar) : "memory");
}
#define MBARRIER_INIT(addr, cnt) \
    asm volatile("mbarrier.init.shared.b64 [%0], %1;" :: "r"(addr), "r"(cnt) : "memory")
#define MBARRIER_ARRIVE(addr) \
    asm volatile("mbarrier.arrive.shared.b64 _, [%0];" :: "r"(addr) : "memory")

__device__ __forceinline__ void mbar_wait(uint32_t mbar, uint32_t parity) {
    uint32_t done;
    asm volatile(
        "{\n\t.reg .pred p;\n\t"
        "mbarrier.try_wait.parity.acquire.cta.shared::cta.b64 p, [%1], %2;\n\t"
        "selp.b32 %0, 1, 0, p;\n\t}"
        : "=r"(done) : "r"(mbar), "r"(parity) : "memory");
    if (!done) {
        asm volatile(
            "{\n\t.reg .pred P1;\n\t"
            "WAIT_LOOP_%=:\n\t"
            "mbarrier.try_wait.parity.acquire.cta.shared::cta.b64 P1, [%0], %1, 0x989680;\n\t"
            "@P1 bra.uni WAIT_DONE_%=;\n\t"
            "bra.uni WAIT_LOOP_%=;\n\t"
            "WAIT_DONE_%=:\n\t}"
            :: "r"(mbar), "r"(parity) : "memory");
    }
}

__device__ __forceinline__ void ldsm_x4(uint32_t& r0, uint32_t& r1, uint32_t& r2, uint32_t& r3,
                                        uint32_t addr) {
    asm volatile("ldmatrix.sync.aligned.m8n8.x4.shared.b16 {%0,%1,%2,%3}, [%4];"
                 : "=r"(r0), "=r"(r1), "=r"(r2), "=r"(r3) : "r"(addr));
}
__device__ __forceinline__ void mma_16816(float& c0, float& c1, float& c2, float& c3,
                                          uint32_t a0, uint32_t a1, uint32_t a2, uint32_t a3,
                                          uint32_t b0, uint32_t b1) {
    asm volatile("mma.sync.aligned.m16n8k16.row.col.f32.f16.f16.f32 "
                 "{%0,%1,%2,%3}, {%4,%5,%6,%7}, {%8,%9}, {%0,%1,%2,%3};"
                 : "+f"(c0), "+f"(c1), "+f"(c2), "+f"(c3)
                 : "r"(a0), "r"(a1), "r"(a2), "r"(a3), "r"(b0), "r"(b1));
}

// ---------------------------------------------------------------------------
// Merged prep: rows [0,C) -> normalize W row; rows [C,C+B) -> normalize X row.
// ---------------------------------------------------------------------------
__global__ void prep_kernel(const float* __restrict__ W, const float* __restrict__ X,
                            int C, int B) {
    int row  = (blockIdx.x * blockDim.x + threadIdx.x) >> 5;
    int lane = threadIdx.x & 31;
    if (row >= C + B) return;
    const bool isx = row >= C;
    const int  r   = isx ? row - C : row;
    const float* src = (isx ? X : W) + (size_t)r * DD;
    __half*      dst = (isx ? g_xh : g_wh) + (size_t)r * DD;

    float4 v0 = *(const float4*)(src + lane * 4);
    float4 v1 = *(const float4*)(src + 128 + lane * 4);
    float s = v0.x*v0.x + v0.y*v0.y + v0.z*v0.z + v0.w*v0.w
            + v1.x*v1.x + v1.y*v1.y + v1.z*v1.z + v1.w*v1.w;
    #pragma unroll
    for (int o = 16; o; o >>= 1) s += __shfl_xor_sync(0xffffffffu, s, o);
    float inv = rsqrtf(s);
    if (isx && lane == 0) g_xlen[r] = s * inv;   // len
    __half2 h0 = __floats2half2_rn(v0.x * inv, v0.y * inv);
    __half2 h1 = __floats2half2_rn(v0.z * inv, v0.w * inv);
    __half2 h2 = __floats2half2_rn(v1.x * inv, v1.y * inv);
    __half2 h3 = __floats2half2_rn(v1.z * inv, v1.w * inv);
    *(__half2*)(dst + lane * 4)           = h0;
    *(__half2*)(dst + lane * 4 + 2)       = h1;
    *(__half2*)(dst + 128 + lane * 4)     = h2;
    *(__half2*)(dst + 128 + lane * 4 + 2) = h3;
}

// ---------------------------------------------------------------------------
// GEMM: CTA 128x128, 256 threads, 8 warps (2m x 4n), warp tile 64x32.
// A fully K-resident; B ring of 3 over K chunks of 64.
// mbarrier producer/consumer pipeline (no __syncthreads in the loop).
// ---------------------------------------------------------------------------
#define BM 128
#define BN 128
#define BK 64
#define NCHUNK (DD / BK)                 // 4

#define A_OFF      0                     // 4 slabs of 16 KB = 65536
#define B_OFF      65536                 // ring 3 x 16 KB = 49152
#define MB_OFF     114688                // 6 mbarriers (full/empty x 3), 16B pairs
#define SMEM_TOTAL 114816                // ~112.1 KB -> 2 CTAs/SM

__global__ __launch_bounds__(256, 2)
void angle_mma_kernel(const int* __restrict__ Y, float* __restrict__ out, int C)
{
    extern __shared__ char smem[];
    const uint32_t sbase = smem_u32(smem);
    const int tid  = threadIdx.x;
    const int wid  = tid >> 5;
    const int lane = tid & 31;
    const int wm   = wid >> 2;     // 0..1 : warp m (64 rows)
    const int wn   = wid & 3;      // 0..3 : warp n (32 cols)

    const int bm = blockIdx.x * BM;
    const int bn = blockIdx.y * BN;

    const uint32_t mb_full0  = sbase + MB_OFF + 0 * 16;
    const uint32_t mb_empty0 = sbase + MB_OFF + 0 * 16 + 8;

    // ---- mbarrier init ----
    if (tid == 0) {
        #pragma unroll
        for (int s = 0; s < 3; s++) {
            MBARRIER_INIT(sbase + MB_OFF + s * 16,     256);  // full[s]
            MBARRIER_INIT(sbase + MB_OFF + s * 16 + 8, 8);    // empty[s]
        }
    }
    __syncthreads();

    // ---- loaders ----
    auto load_a_all = [&]() {       // 128 rows x 256 k, 4 slabs of 16 KB
        for (int i = 0; i < 16; i++) {
            int t2 = tid + i * 256;
            int chunk = t2 >> 10;
            int w3    = t2 & 1023;
            int row = w3 >> 3, blk = w3 & 7;
            uint32_t off = (uint32_t)(row * 128) + (uint32_t)((blk ^ (row & 7)) << 4);
            cp_async16(sbase + A_OFF + chunk * 16384 + off,
                       g_xh + (size_t)(bm + row) * DD + chunk * BK + blk * 8);
        }
    };
    auto load_b = [&](int buf, int kc) {          // 128 rows x 64 k
        const uint32_t bb = sbase + B_OFF + (uint32_t)buf * 16384;
        #pragma unroll
        for (int i = 0; i < 4; i++) {
            int g = tid + i * 256;
            int row = g >> 3, blk = g & 7;
            int rg = bn + row; if (rg >= C) rg = C - 1;
            uint32_t off = (uint32_t)(row * 128) + (uint32_t)((blk ^ (row & 7)) << 4);
            cp_async16(bb + off, g_wh + (size_t)rg * DD + kc + blk * 8);
        }
    };

    // ---- prologue: A + B0 -> full[0]; B1 -> full[1]  (stages fresh: no empty-wait) ----
    load_a_all();
    load_b(0, 0);
    cp_async_mbar_arrive(mb_full0);                       // covers A + B0
    load_b(1, BK);
    cp_async_mbar_arrive(sbase + MB_OFF + 1 * 16);        // covers B1 (and prior)

    float c[4][4][4];
    #pragma unroll
    for (int mt = 0; mt < 4; mt++)
        #pragma unroll
        for (int nt = 0; nt < 4; nt++)
            #pragma unroll
            for (int q = 0; q < 4; q++) c[mt][nt][q] = 0.f;

    // XOR-composable fragment row bases: rel = row*128 + ((row&7)<<4)
    const int a_hi = lane >> 4;
    uint32_t a_rel[4], b_rel[2];
    #pragma unroll
    for (int mt = 0; mt < 4; mt++) {
        int r = wm * 64 + mt * 16 + (lane & 15);
        a_rel[mt] = (uint32_t)(r * 128) + (uint32_t)((r & 7) << 4);
    }
    #pragma unroll
    for (int bt = 0; bt < 2; bt++) {
        int r = wn * 32 + bt * 16 + ((lane >> 3) & 1) * 8 + (lane & 7);
        b_rel[bt] = (uint32_t)(r * 128) + (uint32_t)((r & 7) << 4);
    }

    // ---- main loop: mbarrier pipeline, no __syncthreads ----
    #pragma unroll
    for (int ck = 0; ck < NCHUNK; ck++) {
        const int s = ck % 3;
        // consumer: wait stage full.  parities: ck0..2 -> 0 ; ck3 (s0 reuse) -> 1
        mbar_wait(sbase + MB_OFF + s * 16, (ck == 3) ? 1u : 0u);

        // producer: refill stage (ck+2)%3 with chunk ck+2
        if (ck + 2 < NCHUNK) {
            const int s2 = (ck + 2) % 3;
            if (ck == 1) mbar_wait(mb_empty0, 0);   // s0 reused: wait ck0's readers
            // ck==0 refills s2 (fresh stage, no wait needed)
            load_b(s2, (ck + 2) * BK);
            cp_async_mbar_arrive(sbase + MB_OFF + s2 * 16);
        }

        const uint32_t ab = sbase + A_OFF + (uint32_t)ck * 16384;
        const uint32_t bb = sbase + B_OFF + (uint32_t)s * 16384;

        uint32_t a[2][4][4], b[2][2][4];
        const uint32_t k0 = (uint32_t)(a_hi << 4);
        #pragma unroll
        for (int mt = 0; mt < 4; mt++)
            ldsm_x4(a[0][mt][0], a[0][mt][1], a[0][mt][2], a[0][mt][3],
                    ab + (a_rel[mt] ^ k0));
        #pragma unroll
        for (int bt = 0; bt < 2; bt++)
            ldsm_x4(b[0][bt][0], b[0][bt][1], b[0][bt][2], b[0][bt][3],
                    bb + (b_rel[bt] ^ k0));

        #pragma unroll
        for (int ks = 0; ks < 4; ks++) {
            const int cur = ks & 1, nxt = cur ^ 1;
            if (ks < 3) {
                const uint32_t kc = (uint32_t)(((ks + 1) * 2 + a_hi) << 4);
                #pragma unroll
                for (int mt = 0; mt < 4; mt++)
                    ldsm_x4(a[nxt][mt][0], a[nxt][mt][1], a[nxt][mt][2], a[nxt][mt][3],
                            ab + (a_rel[mt] ^ kc));
                #pragma unroll
                for (int bt = 0; bt < 2; bt++)
                    ldsm_x4(b[nxt][bt][0], b[nxt][bt][1], b[nxt][bt][2], b[nxt][bt][3],
                            bb + (b_rel[bt] ^ kc));
            }
            #pragma unroll
            for (int mt = 0; mt < 4; mt++) {
                #pragma unroll
                for (int nt = 0; nt < 4; nt++) {
                    const int bt = nt >> 1, sub = nt & 1;
                    mma_16816(c[mt][nt][0], c[mt][nt][1], c[mt][nt][2], c[mt][nt][3],
                              a[cur][mt][0], a[cur][mt][1], a[cur][mt][2], a[cur][mt][3],
                              b[cur][bt][sub], b[cur][bt][2 + sub]);
                }
            }
        }

        // consumer done with stage s (warp-uniform point; lane 0 arrives, count=8)
        if (ck == 0 && lane == 0) MBARRIER_ARRIVE(mb_empty0);
        // (empty[1], empty[2], and ck3's empty[0] are never waited on: skip arrives)
    }

    // ---- epilogue: cos -> feat (+ margin at label) ----
    const float inv_pi     = 1.0f / CUDART_PI_F;
    const float inv_1plamb = 1.0f / 1001.0f;

    #pragma unroll
    for (int mt = 0; mt < 4; mt++) {
        const int r0 = bm + wm * 64 + mt * 16 + (lane >> 2);
        const int r1 = r0 + 8;
        const float xl0 = g_xlen[r0], xl1 = g_xlen[r1];
        const int  lab0 = Y[r0],      lab1 = Y[r1];
        #pragma unroll
        for (int nt = 0; nt < 4; nt++) {
            const int col = bn + wn * 32 + nt * 8 + (lane & 3) * 2;
            if (col >= C) continue;          // col even, C even -> col+1 valid
            #pragma unroll
            for (int half = 0; half < 2; half++) {
                const int   rr  = half ? r1 : r0;
                const float xl  = half ? xl1 : xl0;
                const int   lab = half ? lab1 : lab0;
                float v0 = c[mt][nt][half * 2 + 0];
                float v1 = c[mt][nt][half * 2 + 1];
                v0 = fminf(fmaxf(v0, -1.0f), 1.0f);
                v1 = fminf(fmaxf(v1, -1.0f), 1.0f);
                float f0 = v0 * xl, f1 = v1 * xl;
                if (col == lab || col + 1 == lab) {
                    const bool second = (col + 1 == lab);
                    float cv = second ? v1 : v0;
                    float c2   = cv * cv;
                    float cosm = 8.0f * c2 * c2 - 8.0f * c2 + 1.0f;
                    float kf   = floorf(4.0f * acosf(cv) * inv_pi);
                    float sign = 1.0f - 2.0f * fmodf(kf, 2.0f);
                    float phi  = sign * cosm - 2.0f * kf;
                    float fm   = second ? f1 : f0;
                    fm += (phi * xl - fm) * inv_1plamb;
                    if (second) f1 = fm; else f0 = fm;
                }
                *(float2*)(out + (size_t)rr * C + col) = make_float2(f0, f1);
            }
        }
    }
}

// ---------------------------------------------------------------------------
// Launch
// ---------------------------------------------------------------------------
extern "C" void kernel_launch(void* const* d_in, const int* in_sizes, int n_in,
                              void* d_out, int out_size)
{
    const float* x = (const float*)d_in[0];
    const float* w = (const float*)d_in[1];
    const int*   y = (const int*)d_in[2];
    float* out     = (float*)d_out;

    const int B = in_sizes[2];            // 512
    const int D = in_sizes[0] / B;        // 256
    const int C = in_sizes[1] / D;        // 100000
    (void)D;

    static bool attr_set = false;
    if (!attr_set) {
        cudaFuncSetAttribute(angle_mma_kernel,
                             cudaFuncAttributeMaxDynamicSharedMemorySize, SMEM_TOTAL);
        attr_set = true;
    }

    {
        int wpb = 8;
        int rows = C + B;
        prep_kernel<<<(rows + wpb - 1) / wpb, wpb * 32>>>(w, x, C, B);
    }

    // grid.x = m tiles (fastest -> 4 CTAs share each W n-stripe in L2)
    dim3 grid(B / BM, (C + BN - 1) / BN);
    angle_mma_kernel<<<grid, 256, SMEM_TOTAL>>>(y, out, C);
}

// round 13
// speedup vs baseline: 1.0754x; 1.0317x over previous
#include <cuda_runtime.h>
#include <cuda_fp16.h>
#include <math_constants.h>
#include <cstdint>

// Problem constants: B=512, D=256, C=100000, m=4, lambda=1000
#define MAX_C 100000
#define MAX_B 512
#define DD    256

__device__ __half g_wh[(size_t)MAX_C * DD];   // fp16(normalized W)
__device__ __half g_xh[(size_t)MAX_B * DD];   // fp16(normalized X)
__device__ float  g_xlen[MAX_B];

// ---------------------------------------------------------------------------
// Helpers
// ---------------------------------------------------------------------------
__device__ __forceinline__ uint32_t smem_u32(const void* p) {
    uint32_t a;
    asm("{ .reg .u64 t; cvta.to.shared.u64 t, %1; cvt.u32.u64 %0, t; }" : "=r"(a) : "l"(p));
    return a;
}
__device__ __forceinline__ void cp_async16(uint32_t dst, const void* src) {
    asm volatile("cp.async.cg.shared.global [%0], [%1], 16;" :: "r"(dst), "l"(src));
}
__device__ __forceinline__ void cp_commit() {
    asm volatile("cp.async.commit_group;" ::: "memory");
}
template <int N> __device__ __forceinline__ void cp_wait() {
    asm volatile("cp.async.wait_group %0;" :: "n"(N) : "memory");
}
__device__ __forceinline__ void ldsm_x4(uint32_t& r0, uint32_t& r1, uint32_t& r2, uint32_t& r3,
                                        uint32_t addr) {
    asm volatile("ldmatrix.sync.aligned.m8n8.x4.shared.b16 {%0,%1,%2,%3}, [%4];"
                 : "=r"(r0), "=r"(r1), "=r"(r2), "=r"(r3) : "r"(addr));
}
__device__ __forceinline__ void mma_16816(float& c0, float& c1, float& c2, float& c3,
                                          uint32_t a0, uint32_t a1, uint32_t a2, uint32_t a3,
                                          uint32_t b0, uint32_t b1) {
    asm volatile("mma.sync.aligned.m16n8k16.row.col.f32.f16.f16.f32 "
                 "{%0,%1,%2,%3}, {%4,%5,%6,%7}, {%8,%9}, {%0,%1,%2,%3};"
                 : "+f"(c0), "+f"(c1), "+f"(c2), "+f"(c3)
                 : "r"(a0), "r"(a1), "r"(a2), "r"(a3), "r"(b0), "r"(b1));
}
__device__ __forceinline__ void stcs_f2(float* p, float a, float b) {
    asm volatile("st.global.cs.v2.f32 [%0], {%1,%2};" :: "l"(p), "f"(a), "f"(b) : "memory");
}

// ---------------------------------------------------------------------------
// Merged prep: rows [0,C) -> normalize W row; rows [C,C+B) -> normalize X row.
// ---------------------------------------------------------------------------
__global__ void prep_kernel(const float* __restrict__ W, const float* __restrict__ X,
                            int C, int B) {
    int row  = (blockIdx.x * blockDim.x + threadIdx.x) >> 5;
    int lane = threadIdx.x & 31;
    if (row >= C + B) return;
    const bool isx = row >= C;
    const int  r   = isx ? row - C : row;
    const float* src = (isx ? X : W) + (size_t)r * DD;
    __half*      dst = (isx ? g_xh : g_wh) + (size_t)r * DD;

    float4 v0 = *(const float4*)(src + lane * 4);
    float4 v1 = *(const float4*)(src + 128 + lane * 4);
    float s = v0.x*v0.x + v0.y*v0.y + v0.z*v0.z + v0.w*v0.w
            + v1.x*v1.x + v1.y*v1.y + v1.z*v1.z + v1.w*v1.w;
    #pragma unroll
    for (int o = 16; o; o >>= 1) s += __shfl_xor_sync(0xffffffffu, s, o);
    float inv = rsqrtf(s);
    if (isx && lane == 0) g_xlen[r] = s * inv;   // len
    __half2 h0 = __floats2half2_rn(v0.x * inv, v0.y * inv);
    __half2 h1 = __floats2half2_rn(v0.z * inv, v0.w * inv);
    __half2 h2 = __floats2half2_rn(v1.x * inv, v1.y * inv);
    __half2 h3 = __floats2half2_rn(v1.z * inv, v1.w * inv);
    *(__half2*)(dst + lane * 4)           = h0;
    *(__half2*)(dst + lane * 4 + 2)       = h1;
    *(__half2*)(dst + 128 + lane * 4)     = h2;
    *(__half2*)(dst + 128 + lane * 4 + 2) = h3;
}

// ---------------------------------------------------------------------------
// GEMM: CTA 128x128, 256 threads, 8 warps (2m x 4n), warp tile 64x32.
// A fully K-resident (loaded once); B 3-stage ring over K chunks of 64.
// Fragment double-buffering over ks.  Epilogue: batched loads, label fast
// path, streaming stores.
// ---------------------------------------------------------------------------
#define BM 128
#define BN 128
#define BK 64
#define NCHUNK (DD / BK)                 // 4

#define A_OFF      0                     // 4 slabs of 16 KB = 65536
#define B_OFF      65536                 // ring 3 x 16 KB = 49152
#define SMEM_TOTAL 114688                // 112 KB -> 2 CTAs/SM

__global__ __launch_bounds__(256, 2)
void angle_mma_kernel(const int* __restrict__ Y, float* __restrict__ out, int C)
{
    extern __shared__ char smem[];
    const uint32_t sbase = smem_u32(smem);
    const int tid  = threadIdx.x;
    const int wid  = tid >> 5;
    const int lane = tid & 31;
    const int wm   = wid >> 2;     // 0..1 : warp m (64 rows)
    const int wn   = wid & 3;      // 0..3 : warp n (32 cols)

    const int bm = blockIdx.x * BM;
    const int bn = blockIdx.y * BN;

    // ---- loaders ----
    auto load_a_all = [&]() {       // 128 rows x 256 k, 4 slabs of 16 KB
        for (int i = 0; i < 16; i++) {
            int t2 = tid + i * 256;
            int chunk = t2 >> 10;
            int w3    = t2 & 1023;
            int row = w3 >> 3, blk = w3 & 7;
            uint32_t off = (uint32_t)(row * 128) + (uint32_t)((blk ^ (row & 7)) << 4);
            cp_async16(sbase + A_OFF + chunk * 16384 + off,
                       g_xh + (size_t)(bm + row) * DD + chunk * BK + blk * 8);
        }
    };
    auto load_b = [&](int buf, int kc) {          // 128 rows x 64 k
        const uint32_t bb = sbase + B_OFF + (uint32_t)buf * 16384;
        #pragma unroll
        for (int i = 0; i < 4; i++) {
            int g = tid + i * 256;
            int row = g >> 3, blk = g & 7;
            int rg = bn + row; if (rg >= C) rg = C - 1;
            uint32_t off = (uint32_t)(row * 128) + (uint32_t)((blk ^ (row & 7)) << 4);
            cp_async16(bb + off, g_wh + (size_t)rg * DD + kc + blk * 8);
        }
    };

    // ---- prologue: group0 = A + B0, group1 = B1 ----
    load_a_all();
    load_b(0, 0);
    cp_commit();
    load_b(1, BK);
    cp_commit();

    float c[4][4][4];
    #pragma unroll
    for (int mt = 0; mt < 4; mt++)
        #pragma unroll
        for (int nt = 0; nt < 4; nt++)
            #pragma unroll
            for (int q = 0; q < 4; q++) c[mt][nt][q] = 0.f;

    const int a_hi = lane >> 4;
    uint32_t a_rel[4], b_rel[2];
    #pragma unroll
    for (int mt = 0; mt < 4; mt++) {
        int r = wm * 64 + mt * 16 + (lane & 15);
        a_rel[mt] = (uint32_t)(r * 128) + (uint32_t)((r & 7) << 4);
    }
    #pragma unroll
    for (int bt = 0; bt < 2; bt++) {
        int r = wn * 32 + bt * 16 + ((lane >> 3) & 1) * 8 + (lane & 7);
        b_rel[bt] = (uint32_t)(r * 128) + (uint32_t)((r & 7) << 4);
    }

    // ---- main loop: one barrier per chunk; ks-pipelined fragments ----
    #pragma unroll
    for (int ck = 0; ck < NCHUNK; ck++) {
        if (ck == NCHUNK - 1) cp_wait<0>(); else cp_wait<1>();
        __syncthreads();                          // B[ck%3] (+A on ck=0) visible

        if (ck + 2 < NCHUNK) {                    // refill idle 3rd buffer
            load_b((ck + 2) % 3, (ck + 2) * BK);
            cp_commit();
        }

        const uint32_t ab = sbase + A_OFF + (uint32_t)ck * 16384;
        const uint32_t bb = sbase + B_OFF + (uint32_t)(ck % 3) * 16384;

        uint32_t a[2][4][4], b[2][2][4];
        const uint32_t k0 = (uint32_t)(a_hi << 4);
        #pragma unroll
        for (int mt = 0; mt < 4; mt++)
            ldsm_x4(a[0][mt][0], a[0][mt][1], a[0][mt][2], a[0][mt][3],
                    ab + (a_rel[mt] ^ k0));
        #pragma unroll
        for (int bt = 0; bt < 2; bt++)
            ldsm_x4(b[0][bt][0], b[0][bt][1], b[0][bt][2], b[0][bt][3],
                    bb + (b_rel[bt] ^ k0));

        #pragma unroll
        for (int ks = 0; ks < 4; ks++) {
            const int cur = ks & 1, nxt = cur ^ 1;
            if (ks < 3) {
                const uint32_t kc = (uint32_t)(((ks + 1) * 2 + a_hi) << 4);
                #pragma unroll
                for (int mt = 0; mt < 4; mt++)
                    ldsm_x4(a[nxt][mt][0], a[nxt][mt][1], a[nxt][mt][2], a[nxt][mt][3],
                            ab + (a_rel[mt] ^ kc));
                #pragma unroll
                for (int bt = 0; bt < 2; bt++)
                    ldsm_x4(b[nxt][bt][0], b[nxt][bt][1], b[nxt][bt][2], b[nxt][bt][3],
                            bb + (b_rel[bt] ^ kc));
            }
            #pragma unroll
            for (int mt = 0; mt < 4; mt++) {
                #pragma unroll
                for (int nt = 0; nt < 4; nt++) {
                    const int bt = nt >> 1, sub = nt & 1;
                    mma_16816(c[mt][nt][0], c[mt][nt][1], c[mt][nt][2], c[mt][nt][3],
                              a[cur][mt][0], a[cur][mt][1], a[cur][mt][2], a[cur][mt][3],
                              b[cur][bt][sub], b[cur][bt][2 + sub]);
                }
            }
        }
    }

    // ---- epilogue: batched loads, label fast path, streaming stores ----
    const float inv_pi     = 1.0f / CUDART_PI_F;
    const float inv_1plamb = 1.0f / 1001.0f;

    float xl[8]; int lab[8];
    #pragma unroll
    for (int mt = 0; mt < 4; mt++) {
        const int r0 = bm + wm * 64 + mt * 16 + (lane >> 2);
        xl[2 * mt]     = g_xlen[r0];
        xl[2 * mt + 1] = g_xlen[r0 + 8];
        lab[2 * mt]     = Y[r0];
        lab[2 * mt + 1] = Y[r0 + 8];
    }

    #pragma unroll
    for (int mt = 0; mt < 4; mt++) {
        #pragma unroll
        for (int half = 0; half < 2; half++) {
            const int   rr  = bm + wm * 64 + mt * 16 + (lane >> 2) + half * 8;
            const float xlv = xl[2 * mt + half];
            const int   lbv = lab[2 * mt + half];
            float* rowp = out + (size_t)rr * C;
            const bool hit = ((unsigned)(lbv - bn) < (unsigned)BN);

            if (!hit) {
                // fast path: no label in this n-tile for this row
                #pragma unroll
                for (int nt = 0; nt < 4; nt++) {
                    const int col = bn + wn * 32 + nt * 8 + (lane & 3) * 2;
                    if (col >= C) continue;      // col even, C even -> col+1 valid
                    float v0 = c[mt][nt][half * 2 + 0];
                    float v1 = c[mt][nt][half * 2 + 1];
                    v0 = fminf(fmaxf(v0, -1.0f), 1.0f);
                    v1 = fminf(fmaxf(v1, -1.0f), 1.0f);
                    stcs_f2(rowp + col, v0 * xlv, v1 * xlv);
                }
            } else {
                #pragma unroll
                for (int nt = 0; nt < 4; nt++) {
                    const int col = bn + wn * 32 + nt * 8 + (lane & 3) * 2;
                    if (col >= C) continue;
                    float v0 = c[mt][nt][half * 2 + 0];
                    float v1 = c[mt][nt][half * 2 + 1];
                    v0 = fminf(fmaxf(v0, -1.0f), 1.0f);
                    v1 = fminf(fmaxf(v1, -1.0f), 1.0f);
                    float f0 = v0 * xlv, f1 = v1 * xlv;
                    if (col == lbv || col + 1 == lbv) {
                        const bool second = (col + 1 == lbv);
                        float cv = second ? v1 : v0;
                        float c2   = cv * cv;
                        float cosm = 8.0f * c2 * c2 - 8.0f * c2 + 1.0f;
                        float kf   = floorf(4.0f * acosf(cv) * inv_pi);
                        float sign = 1.0f - 2.0f * fmodf(kf, 2.0f);
                        float phi  = sign * cosm - 2.0f * kf;
                        float fm   = second ? f1 : f0;
                        fm += (phi * xlv - fm) * inv_1plamb;
                        if (second) f1 = fm; else f0 = fm;
                    }
                    stcs_f2(rowp + col, f0, f1);
                }
            }
        }
    }
}

// ---------------------------------------------------------------------------
// Launch
// ---------------------------------------------------------------------------
extern "C" void kernel_launch(void* const* d_in, const int* in_sizes, int n_in,
                              void* d_out, int out_size)
{
    const float* x = (const float*)d_in[0];
    const float* w = (const float*)d_in[1];
    const int*   y = (const int*)d_in[2];
    float* out     = (float*)d_out;

    const int B = in_sizes[2];            // 512
    const int D = in_sizes[0] / B;        // 256
    const int C = in_sizes[1] / D;        // 100000
    (void)D;

    static bool attr_set = false;
    if (!attr_set) {
        cudaFuncSetAttribute(angle_mma_kernel,
                             cudaFuncAttributeMaxDynamicSharedMemorySize, SMEM_TOTAL);
        attr_set = true;
    }

    {
        int wpb = 8;
        int rows = C + B;
        prep_kernel<<<(rows + wpb - 1) / wpb, wpb * 32>>>(w, x, C, B);
    }

    // grid.x = m tiles (fastest -> 4 CTAs share each W n-stripe in L2)
    dim3 grid(B / BM, (C + BN - 1) / BN);
    angle_mma_kernel<<<grid, 256, SMEM_TOTAL>>>(y, out, C);
}